// round 2
// baseline (speedup 1.0000x reference)
#include <cuda_runtime.h>
#include <cuda_bf16.h>
#include <cstdint>

// Problem constants (fixed by the dataset):
//   N = 100000 nodes, E = 1,600,000 edges, F_IN = 256, F_OUT = 128
// d_in order: input_features [N*256] f32, edge_rows [E] i32, edge_cols [E] i32,
//             edge_vals [E] f32, W [128*256] f32, b [128] f32
// d_out: [N*128] f32

#define F_IN   256
#define F_OUT  128
#define MAX_N  100000

// Scratch for the dense "transformed = X @ W^T + b" result (51.2 MB).
__device__ float g_transformed[(size_t)MAX_N * F_OUT];

// ---------------------------------------------------------------------------
// Phase 1: fp32 tiled GEMM  T[m][o] = sum_k X[m][k] * W[o][k] + b[o]
// Tile 128x128, BK=16, 256 threads, 8x8 register micro-tile per thread.
// ---------------------------------------------------------------------------
#define BM 128
#define BN 128
#define BK 16

__global__ __launch_bounds__(256) void gemm_bias_kernel(
    const float* __restrict__ X,
    const float* __restrict__ W,
    const float* __restrict__ bias,
    int M)
{
    __shared__ __align__(16) float Xs[BK][BM + 4];
    __shared__ __align__(16) float Ws[BK][BN + 4];

    const int tid = threadIdx.x;
    const int tx  = tid & 15;   // 0..15 -> output-feature octet
    const int ty  = tid >> 4;   // 0..15 -> row octet
    const int m0  = blockIdx.x * BM;

    // global->smem load mapping: 512 float4 per tile per operand, 2 per thread
    const int lr = tid >> 2;          // 0..63
    const int lc = (tid & 3) << 2;    // 0,4,8,12  (k-offset within tile)

    float acc[8][8];
#pragma unroll
    for (int i = 0; i < 8; ++i)
#pragma unroll
        for (int j = 0; j < 8; ++j) acc[i][j] = 0.0f;

    for (int k0 = 0; k0 < F_IN; k0 += BK) {
#pragma unroll
        for (int h = 0; h < 2; ++h) {
            const int mrow = m0 + lr + h * 64;
            float4 xv = make_float4(0.f, 0.f, 0.f, 0.f);
            if (mrow < M)
                xv = *(const float4*)(X + (size_t)mrow * F_IN + k0 + lc);
            Xs[lc + 0][lr + h * 64] = xv.x;
            Xs[lc + 1][lr + h * 64] = xv.y;
            Xs[lc + 2][lr + h * 64] = xv.z;
            Xs[lc + 3][lr + h * 64] = xv.w;

            const int orow = lr + h * 64;   // always < 128
            const float4 wv = *(const float4*)(W + (size_t)orow * F_IN + k0 + lc);
            Ws[lc + 0][orow] = wv.x;
            Ws[lc + 1][orow] = wv.y;
            Ws[lc + 2][orow] = wv.z;
            Ws[lc + 3][orow] = wv.w;
        }
        __syncthreads();

#pragma unroll
        for (int kk = 0; kk < BK; ++kk) {
            float a[8], bb[8];
            *(float4*)&a[0]  = *(const float4*)&Xs[kk][ty * 8];
            *(float4*)&a[4]  = *(const float4*)&Xs[kk][ty * 8 + 4];
            *(float4*)&bb[0] = *(const float4*)&Ws[kk][tx * 8];
            *(float4*)&bb[4] = *(const float4*)&Ws[kk][tx * 8 + 4];
#pragma unroll
            for (int i = 0; i < 8; ++i)
#pragma unroll
                for (int j = 0; j < 8; ++j)
                    acc[i][j] = fmaf(a[i], bb[j], acc[i][j]);
        }
        __syncthreads();
    }

    // epilogue: add bias, write transformed
    const float4 b0 = *(const float4*)&bias[tx * 8];
    const float4 b1 = *(const float4*)&bias[tx * 8 + 4];
#pragma unroll
    for (int i = 0; i < 8; ++i) {
        const int m = m0 + ty * 8 + i;
        if (m < M) {
            float4 o0, o1;
            o0.x = acc[i][0] + b0.x; o0.y = acc[i][1] + b0.y;
            o0.z = acc[i][2] + b0.z; o0.w = acc[i][3] + b0.w;
            o1.x = acc[i][4] + b1.x; o1.y = acc[i][5] + b1.y;
            o1.z = acc[i][6] + b1.z; o1.w = acc[i][7] + b1.w;
            float* dst = &g_transformed[(size_t)m * F_OUT + tx * 8];
            *(float4*)dst       = o0;
            *(float4*)(dst + 4) = o1;
        }
    }
}

// ---------------------------------------------------------------------------
// Phase 2: edge scatter.  One warp per edge:
//   out[row] += val * transformed[col]   (128 floats = 1 float4 per lane)
// Uses vectorized reduction red.global.add.v4.f32 (sm_90+).
// ---------------------------------------------------------------------------
__global__ __launch_bounds__(256) void spmm_scatter_kernel(
    const int*   __restrict__ rows,
    const int*   __restrict__ cols,
    const float* __restrict__ vals,
    float*       __restrict__ out,
    int E)
{
    const int warp = (int)((blockIdx.x * (unsigned)blockDim.x + threadIdx.x) >> 5);
    const int lane = threadIdx.x & 31;
    if (warp >= E) return;

    const int   r = __ldg(&rows[warp]);
    const int   c = __ldg(&cols[warp]);
    const float v = __ldg(&vals[warp]);

    const float4 t = __ldg((const float4*)(g_transformed + (size_t)c * F_OUT) + lane);

    float* dst = out + (size_t)r * F_OUT + lane * 4;
    asm volatile(
        "red.global.add.v4.f32 [%0], {%1, %2, %3, %4};"
        :
        : "l"(dst), "f"(t.x * v), "f"(t.y * v), "f"(t.z * v), "f"(t.w * v)
        : "memory");
}

// ---------------------------------------------------------------------------
// Launch
// ---------------------------------------------------------------------------
extern "C" void kernel_launch(void* const* d_in, const int* in_sizes, int n_in,
                              void* d_out, int out_size)
{
    const float* X    = (const float*)d_in[0];
    const int*   er   = (const int*)  d_in[1];
    const int*   ec   = (const int*)  d_in[2];
    const float* ev   = (const float*)d_in[3];
    const float* W    = (const float*)d_in[4];
    const float* bias = (const float*)d_in[5];
    float* out = (float*)d_out;

    const int M = in_sizes[0] / F_IN;   // 100000
    const int E = in_sizes[1];          // 1600000

    // out is poisoned; the scatter accumulates, so zero it first.
    cudaMemsetAsync(d_out, 0, (size_t)out_size * sizeof(float));

    gemm_bias_kernel<<<(M + BM - 1) / BM, 256>>>(X, W, bias, M);

    const int warps_per_block = 256 / 32;
    const int blocks = (E + warps_per_block - 1) / warps_per_block;
    spmm_scatter_kernel<<<blocks, 256>>>(er, ec, ev, out, E);
}

// round 3
// speedup vs baseline: 1.6505x; 1.6505x over previous
#include <cuda_runtime.h>
#include <cuda_bf16.h>
#include <cstdint>

// N = 100000, E = 1,600,000, F_IN = 256, F_OUT = 128
// d_in: X [N*256] f32, edge_rows [E] i32, edge_cols [E] i32, edge_vals [E] f32,
//       W [128*256] f32, b [128] f32.  d_out: [N*128] f32.

#define F_IN   256
#define F_OUT  128
#define MAX_N  100000
#define MAX_E  1600000

// -------------------- device scratch (no allocs allowed) --------------------
__device__ float g_transformed[(size_t)MAX_N * F_OUT];   // 51.2 MB
__device__ int   g_counts[MAX_N];                        // per-row degree
__device__ int   g_offsets[MAX_N];                       // excl. scan; after fill = segment END
__device__ int   g_chunksums[256];
__device__ int2  g_sorted[MAX_E];                        // (col, val_bits) grouped by row

// ============================================================================
// Phase 1: TF32 tensor-core GEMM   T[m][o] = sum_k X[m][k]*W[o][k] + b[o]
// Block tile 128x128, BK=32, 256 threads (8 warps), warp tile 64x32,
// mma.sync.m16n8k8 (4 m-tiles x 4 n-tiles per warp).
// ============================================================================
#define BM 128
#define BN 128
#define BK 32
#define BKP 36   // padded smem row stride (floats)

__device__ __forceinline__ float to_tf32(float f) {
    unsigned u;
    asm("cvt.rna.tf32.f32 %0, %1;" : "=r"(u) : "f"(f));
    return __uint_as_float(u);
}

// k-permutation inside each 8-wide k-step group so that (k, k+4) are adjacent
// -> fragment loads become float2 (LDS.64).
__device__ __forceinline__ int kperm(int kk) {
    return ((kk >> 3) << 3) + ((kk & 3) << 1) + ((kk >> 2) & 1);
}

__device__ __forceinline__ void mma_tf32(
    float& c0, float& c1, float& c2, float& c3,
    unsigned a0, unsigned a1, unsigned a2, unsigned a3,
    unsigned b0, unsigned b1)
{
    asm volatile(
        "mma.sync.aligned.m16n8k8.row.col.f32.tf32.tf32.f32 "
        "{%0,%1,%2,%3}, {%4,%5,%6,%7}, {%8,%9}, {%0,%1,%2,%3};"
        : "+f"(c0), "+f"(c1), "+f"(c2), "+f"(c3)
        : "r"(a0), "r"(a1), "r"(a2), "r"(a3), "r"(b0), "r"(b1));
}

__global__ __launch_bounds__(256) void gemm_tf32_kernel(
    const float* __restrict__ X,
    const float* __restrict__ W,
    const float* __restrict__ bias,
    int M)
{
    __shared__ __align__(16) float Xs[BM][BKP];
    __shared__ __align__(16) float Ws[BN][BKP];

    const int tid    = threadIdx.x;
    const int wid    = tid >> 5;
    const int lane   = tid & 31;
    const int warp_m = wid & 1;    // 2 warps in m: 64 rows each
    const int warp_n = wid >> 1;   // 4 warps in n: 32 cols each
    const int g4     = lane >> 2;
    const int tig    = lane & 3;
    const int m0     = blockIdx.x * BM;

    // loader mapping: thread -> (row, 16-wide k half)
    const int lrow  = tid >> 1;
    const int lkb   = (tid & 1) << 4;   // 0 or 16

    float c[4][4][4];
#pragma unroll
    for (int mt = 0; mt < 4; ++mt)
#pragma unroll
        for (int nt = 0; nt < 4; ++nt)
#pragma unroll
            for (int i = 0; i < 4; ++i) c[mt][nt][i] = 0.0f;

    for (int k0 = 0; k0 < F_IN; k0 += BK) {
        // ---- load X tile (guard rows) and W tile (always valid) ----
        {
            float xv[16];
            const int mrow = m0 + lrow;
            if (mrow < M) {
                const float* p = X + (size_t)mrow * F_IN + k0 + lkb;
                *(float4*)&xv[0]  = *(const float4*)(p + 0);
                *(float4*)&xv[4]  = *(const float4*)(p + 4);
                *(float4*)&xv[8]  = *(const float4*)(p + 8);
                *(float4*)&xv[12] = *(const float4*)(p + 12);
            } else {
#pragma unroll
                for (int i = 0; i < 16; ++i) xv[i] = 0.0f;
            }
            float wv[16];
            const float* q = W + (size_t)lrow * F_IN + k0 + lkb;
            *(float4*)&wv[0]  = *(const float4*)(q + 0);
            *(float4*)&wv[4]  = *(const float4*)(q + 4);
            *(float4*)&wv[8]  = *(const float4*)(q + 8);
            *(float4*)&wv[12] = *(const float4*)(q + 12);
#pragma unroll
            for (int i = 0; i < 16; ++i) {
                const int col = kperm(lkb + i);
                Xs[lrow][col] = to_tf32(xv[i]);
                Ws[lrow][col] = to_tf32(wv[i]);
            }
        }
        __syncthreads();

        // ---- 4 k-steps of 8 ----
#pragma unroll
        for (int g = 0; g < 4; ++g) {
            const int kc = (g << 3) + (tig << 1);
            unsigned b0[4], b1[4];
#pragma unroll
            for (int nt = 0; nt < 4; ++nt) {
                const float2 bv = *(const float2*)&Ws[warp_n * 32 + nt * 8 + g4][kc];
                b0[nt] = __float_as_uint(bv.x);
                b1[nt] = __float_as_uint(bv.y);
            }
#pragma unroll
            for (int mt = 0; mt < 4; ++mt) {
                const int r = warp_m * 64 + mt * 16 + g4;
                const float2 aA = *(const float2*)&Xs[r][kc];
                const float2 aB = *(const float2*)&Xs[r + 8][kc];
                const unsigned a0 = __float_as_uint(aA.x);  // (row, k)
                const unsigned a2 = __float_as_uint(aA.y);  // (row, k+4)
                const unsigned a1 = __float_as_uint(aB.x);  // (row+8, k)
                const unsigned a3 = __float_as_uint(aB.y);  // (row+8, k+4)
#pragma unroll
                for (int nt = 0; nt < 4; ++nt)
                    mma_tf32(c[mt][nt][0], c[mt][nt][1], c[mt][nt][2], c[mt][nt][3],
                             a0, a1, a2, a3, b0[nt], b1[nt]);
            }
        }
        __syncthreads();
    }

    // ---- epilogue: bias + store ----
#pragma unroll
    for (int nt = 0; nt < 4; ++nt) {
        const int col = warp_n * 32 + nt * 8 + tig * 2;
        const float bx = bias[col], by = bias[col + 1];
#pragma unroll
        for (int mt = 0; mt < 4; ++mt) {
            const int row = m0 + warp_m * 64 + mt * 16 + g4;
            if (row < M) {
                float2 o0 = make_float2(c[mt][nt][0] + bx, c[mt][nt][1] + by);
                *(float2*)&g_transformed[(size_t)row * F_OUT + col] = o0;
            }
            if (row + 8 < M) {
                float2 o1 = make_float2(c[mt][nt][2] + bx, c[mt][nt][3] + by);
                *(float2*)&g_transformed[(size_t)(row + 8) * F_OUT + col] = o1;
            }
        }
    }
}

// ============================================================================
// Phase 2: on-the-fly CSR build + warp-per-row gather (no float atomics)
// ============================================================================
__global__ void zero_counts_kernel(int n) {
    int i = blockIdx.x * blockDim.x + threadIdx.x;
    if (i < n) g_counts[i] = 0;
}

__global__ void hist_kernel(const int* __restrict__ rows, int E) {
    int i = blockIdx.x * blockDim.x + threadIdx.x;
    if (i < E) atomicAdd(&g_counts[rows[i]], 1);
}

// per-1024 chunk exclusive scan of counts -> offsets; chunk totals -> chunksums
__global__ __launch_bounds__(1024) void scan1_kernel(int n) {
    __shared__ int sh[1024];
    const int t = threadIdx.x;
    const int gid = blockIdx.x * 1024 + t;
    const int v = (gid < n) ? g_counts[gid] : 0;
    sh[t] = v;
    __syncthreads();
#pragma unroll
    for (int d = 1; d < 1024; d <<= 1) {
        int add = (t >= d) ? sh[t - d] : 0;
        __syncthreads();
        sh[t] += add;
        __syncthreads();
    }
    if (gid < n) g_offsets[gid] = sh[t] - v;  // exclusive
    if (t == 1023) g_chunksums[blockIdx.x] = sh[t];
}

__global__ void scan2_kernel(int nchunks) {
    __shared__ int sh[256];
    const int t = threadIdx.x;
    sh[t] = (t < nchunks) ? g_chunksums[t] : 0;
    __syncthreads();
    if (t == 0) {
        int acc = 0;
        for (int i = 0; i < nchunks; ++i) { int cc = sh[i]; sh[i] = acc; acc += cc; }
    }
    __syncthreads();
    if (t < nchunks) g_chunksums[t] = sh[t];
}

__global__ void scan3_kernel(int n) {
    int i = blockIdx.x * blockDim.x + threadIdx.x;
    if (i < n) g_offsets[i] += g_chunksums[i >> 10];
}

// scatter edges into row-grouped order; g_offsets[r] advances to segment END
__global__ void fill_kernel(const int* __restrict__ rows,
                            const int* __restrict__ cols,
                            const float* __restrict__ vals, int E) {
    int e = blockIdx.x * blockDim.x + threadIdx.x;
    if (e < E) {
        const int r = rows[e];
        const int pos = atomicAdd(&g_offsets[r], 1);
        g_sorted[pos] = make_int2(cols[e], __float_as_int(vals[e]));
    }
}

// one warp per output row: out[r] = sum val * transformed[col]
__global__ __launch_bounds__(256) void gather_kernel(float* __restrict__ out, int N) {
    const int warp = (int)((blockIdx.x * (unsigned)blockDim.x + threadIdx.x) >> 5);
    const int lane = threadIdx.x & 31;
    if (warp >= N) return;

    const int end = g_offsets[warp];          // post-fill = segment end
    const int cnt = g_counts[warp];
    int i = end - cnt;

    float4 acc = make_float4(0.f, 0.f, 0.f, 0.f);
    if (i < end) {
        int2 e = g_sorted[i];                 // broadcast load
        while (i < end) {
            const int2 cur = e;
            ++i;
            if (i < end) e = g_sorted[i];     // prefetch next edge
            const float v = __int_as_float(cur.y);
            const float4 t =
                *((const float4*)(g_transformed + (size_t)cur.x * F_OUT) + lane);
            acc.x = fmaf(v, t.x, acc.x);
            acc.y = fmaf(v, t.y, acc.y);
            acc.z = fmaf(v, t.z, acc.z);
            acc.w = fmaf(v, t.w, acc.w);
        }
    }
    *((float4*)(out + (size_t)warp * F_OUT) + lane) = acc;  // rows w/o edges -> zeros
}

// ============================================================================
// Launch
// ============================================================================
extern "C" void kernel_launch(void* const* d_in, const int* in_sizes, int n_in,
                              void* d_out, int out_size)
{
    const float* X    = (const float*)d_in[0];
    const int*   er   = (const int*)  d_in[1];
    const int*   ec   = (const int*)  d_in[2];
    const float* ev   = (const float*)d_in[3];
    const float* W    = (const float*)d_in[4];
    const float* bias = (const float*)d_in[5];
    float* out = (float*)d_out;

    const int M = in_sizes[0] / F_IN;   // 100000
    const int E = in_sizes[1];          // 1600000
    const int nchunks = (M + 1023) / 1024;

    // GEMM (independent of CSR build; same stream so order is arbitrary here)
    gemm_tf32_kernel<<<(M + BM - 1) / BM, 256>>>(X, W, bias, M);

    // CSR build
    zero_counts_kernel<<<(M + 255) / 256, 256>>>(M);
    hist_kernel<<<(E + 255) / 256, 256>>>(er, E);
    scan1_kernel<<<nchunks, 1024>>>(M);
    scan2_kernel<<<1, 256>>>(nchunks);
    scan3_kernel<<<(M + 255) / 256, 256>>>(M);
    fill_kernel<<<(E + 255) / 256, 256>>>(er, ec, ev, E);

    // row-major reduction, each output row written exactly once
    const int gwarps_per_block = 256 / 32;
    gather_kernel<<<(M + gwarps_per_block - 1) / gwarps_per_block, 256>>>(out, M);
}

// round 4
// speedup vs baseline: 1.9808x; 1.2001x over previous
#include <cuda_runtime.h>
#include <cuda_bf16.h>
#include <cuda_fp16.h>
#include <cstdint>

// N = 100000, E = 1,600,000, F_IN = 256, F_OUT = 128
// d_in: X [N*256] f32, edge_rows [E] i32, edge_cols [E] i32, edge_vals [E] f32,
//       W [128*256] f32, b [128] f32.  d_out: [N*128] f32.

#define F_IN   256
#define F_OUT  128
#define MAX_N  100000
#define MAX_E  1600000

// -------------------- device scratch (no allocs allowed) --------------------
__device__ __half2 g_th[(size_t)MAX_N * (F_OUT / 2)];   // transformed, fp16 (25.6 MB)
__device__ int   g_counts[MAX_N];                        // per-row degree
__device__ int   g_offsets[MAX_N];                       // chunk-local excl scan; after fill = chunk-local END
__device__ int   g_chunksums[256];                       // chunk bases (after scan2)
__device__ int2  g_sorted[MAX_E];                        // (col, val_bits) grouped by row

// ============================================================================
// Phase 1: TF32 tensor-core GEMM   T[m][o] = sum_k X[m][k]*W[o][k] + b[o]
// Block tile 128x128, BK=32, 256 threads (8 warps), warp tile 64x32,
// mma.sync.m16n8k8. Epilogue stores fp16.
// ============================================================================
#define BM 128
#define BN 128
#define BK 32
#define BKP 36   // padded smem row stride (floats)

__device__ __forceinline__ float to_tf32(float f) {
    unsigned u;
    asm("cvt.rna.tf32.f32 %0, %1;" : "=r"(u) : "f"(f));
    return __uint_as_float(u);
}

// k-permutation inside each 8-wide k-step group so that (k, k+4) are adjacent
// -> fragment loads become float2 (LDS.64).
__device__ __forceinline__ int kperm(int kk) {
    return ((kk >> 3) << 3) + ((kk & 3) << 1) + ((kk >> 2) & 1);
}

__device__ __forceinline__ void mma_tf32(
    float& c0, float& c1, float& c2, float& c3,
    unsigned a0, unsigned a1, unsigned a2, unsigned a3,
    unsigned b0, unsigned b1)
{
    asm volatile(
        "mma.sync.aligned.m16n8k8.row.col.f32.tf32.tf32.f32 "
        "{%0,%1,%2,%3}, {%4,%5,%6,%7}, {%8,%9}, {%0,%1,%2,%3};"
        : "+f"(c0), "+f"(c1), "+f"(c2), "+f"(c3)
        : "r"(a0), "r"(a1), "r"(a2), "r"(a3), "r"(b0), "r"(b1));
}

__global__ __launch_bounds__(256) void gemm_tf32_kernel(
    const float* __restrict__ X,
    const float* __restrict__ W,
    const float* __restrict__ bias,
    int M)
{
    __shared__ __align__(16) float Xs[BM][BKP];
    __shared__ __align__(16) float Ws[BN][BKP];

    const int tid    = threadIdx.x;
    const int wid    = tid >> 5;
    const int lane   = tid & 31;
    const int warp_m = wid & 1;    // 2 warps in m: 64 rows each
    const int warp_n = wid >> 1;   // 4 warps in n: 32 cols each
    const int g4     = lane >> 2;
    const int tig    = lane & 3;
    const int m0     = blockIdx.x * BM;

    const int lrow  = tid >> 1;
    const int lkb   = (tid & 1) << 4;   // 0 or 16

    float c[4][4][4];
#pragma unroll
    for (int mt = 0; mt < 4; ++mt)
#pragma unroll
        for (int nt = 0; nt < 4; ++nt)
#pragma unroll
            for (int i = 0; i < 4; ++i) c[mt][nt][i] = 0.0f;

    for (int k0 = 0; k0 < F_IN; k0 += BK) {
        {
            float xv[16];
            const int mrow = m0 + lrow;
            if (mrow < M) {
                const float* p = X + (size_t)mrow * F_IN + k0 + lkb;
                *(float4*)&xv[0]  = *(const float4*)(p + 0);
                *(float4*)&xv[4]  = *(const float4*)(p + 4);
                *(float4*)&xv[8]  = *(const float4*)(p + 8);
                *(float4*)&xv[12] = *(const float4*)(p + 12);
            } else {
#pragma unroll
                for (int i = 0; i < 16; ++i) xv[i] = 0.0f;
            }
            float wv[16];
            const float* q = W + (size_t)lrow * F_IN + k0 + lkb;
            *(float4*)&wv[0]  = *(const float4*)(q + 0);
            *(float4*)&wv[4]  = *(const float4*)(q + 4);
            *(float4*)&wv[8]  = *(const float4*)(q + 8);
            *(float4*)&wv[12] = *(const float4*)(q + 12);
#pragma unroll
            for (int i = 0; i < 16; ++i) {
                const int col = kperm(lkb + i);
                Xs[lrow][col] = to_tf32(xv[i]);
                Ws[lrow][col] = to_tf32(wv[i]);
            }
        }
        __syncthreads();

#pragma unroll
        for (int g = 0; g < 4; ++g) {
            const int kc = (g << 3) + (tig << 1);
            unsigned b0[4], b1[4];
#pragma unroll
            for (int nt = 0; nt < 4; ++nt) {
                const float2 bv = *(const float2*)&Ws[warp_n * 32 + nt * 8 + g4][kc];
                b0[nt] = __float_as_uint(bv.x);
                b1[nt] = __float_as_uint(bv.y);
            }
#pragma unroll
            for (int mt = 0; mt < 4; ++mt) {
                const int r = warp_m * 64 + mt * 16 + g4;
                const float2 aA = *(const float2*)&Xs[r][kc];
                const float2 aB = *(const float2*)&Xs[r + 8][kc];
                const unsigned a0 = __float_as_uint(aA.x);
                const unsigned a2 = __float_as_uint(aA.y);
                const unsigned a1 = __float_as_uint(aB.x);
                const unsigned a3 = __float_as_uint(aB.y);
#pragma unroll
                for (int nt = 0; nt < 4; ++nt)
                    mma_tf32(c[mt][nt][0], c[mt][nt][1], c[mt][nt][2], c[mt][nt][3],
                             a0, a1, a2, a3, b0[nt], b1[nt]);
            }
        }
        __syncthreads();
    }

    // ---- epilogue: bias + fp16 store ----
#pragma unroll
    for (int nt = 0; nt < 4; ++nt) {
        const int col = warp_n * 32 + nt * 8 + tig * 2;
        const float bx = bias[col], by = bias[col + 1];
#pragma unroll
        for (int mt = 0; mt < 4; ++mt) {
            const int row = m0 + warp_m * 64 + mt * 16 + g4;
            if (row < M) {
                g_th[(size_t)row * (F_OUT / 2) + (col >> 1)] =
                    __floats2half2_rn(c[mt][nt][0] + bx, c[mt][nt][1] + by);
            }
            if (row + 8 < M) {
                g_th[(size_t)(row + 8) * (F_OUT / 2) + (col >> 1)] =
                    __floats2half2_rn(c[mt][nt][2] + bx, c[mt][nt][3] + by);
            }
        }
    }
}

// ============================================================================
// Phase 2: CSR build + warp-per-row gather (no float atomics)
// ============================================================================
__global__ void zero_counts_kernel(int n) {
    int i = blockIdx.x * blockDim.x + threadIdx.x;
    if (i < n) g_counts[i] = 0;
}

__global__ void hist_kernel(const int* __restrict__ rows, int E) {
    int i = blockIdx.x * blockDim.x + threadIdx.x;
    if (i < E) atomicAdd(&g_counts[rows[i]], 1);
}

// per-1024 chunk exclusive scan of counts -> offsets (shuffle-based)
__global__ __launch_bounds__(1024) void scan1_kernel(int n) {
    __shared__ int wsum[32];
    const int t   = threadIdx.x;
    const int gid = blockIdx.x * 1024 + t;
    const int v   = (gid < n) ? g_counts[gid] : 0;

    int x = v;
#pragma unroll
    for (int d = 1; d < 32; d <<= 1) {
        int y = __shfl_up_sync(0xffffffffu, x, d);
        if ((t & 31) >= d) x += y;
    }
    if ((t & 31) == 31) wsum[t >> 5] = x;
    __syncthreads();
    if (t < 32) {
        int s = wsum[t];
#pragma unroll
        for (int d = 1; d < 32; d <<= 1) {
            int y = __shfl_up_sync(0xffffffffu, s, d);
            if (t >= d) s += y;
        }
        wsum[t] = s;   // inclusive warp sums
    }
    __syncthreads();
    const int base = (t >= 32) ? wsum[(t >> 5) - 1] : 0;
    const int incl = x + base;
    if (gid < n) g_offsets[gid] = incl - v;         // chunk-local exclusive
    if (t == 1023) g_chunksums[blockIdx.x] = incl;  // chunk total
}

__global__ void scan2_kernel(int nchunks) {
    __shared__ int sh[256];
    const int t = threadIdx.x;
    sh[t] = (t < nchunks) ? g_chunksums[t] : 0;
    __syncthreads();
    if (t == 0) {
        int acc = 0;
        for (int i = 0; i < nchunks; ++i) { int cc = sh[i]; sh[i] = acc; acc += cc; }
    }
    __syncthreads();
    if (t < nchunks) g_chunksums[t] = sh[t];   // exclusive chunk bases
}

// scatter edges into row-grouped order (chunk base folded in here)
__global__ void fill_kernel(const int* __restrict__ rows,
                            const int* __restrict__ cols,
                            const float* __restrict__ vals, int E) {
    int e = blockIdx.x * blockDim.x + threadIdx.x;
    if (e < E) {
        const int r = rows[e];
        const int pos = atomicAdd(&g_offsets[r], 1) + g_chunksums[r >> 10];
        g_sorted[pos] = make_int2(cols[e], __float_as_int(vals[e]));
    }
}

// one warp per output row: out[r] = sum val * transformed_fp16[col]
__global__ __launch_bounds__(256) void gather_kernel(float* __restrict__ out, int N) {
    const int warp = (int)((blockIdx.x * (unsigned)blockDim.x + threadIdx.x) >> 5);
    const int lane = threadIdx.x & 31;
    if (warp >= N) return;

    const int cnt = g_counts[warp];
    const int end = g_offsets[warp] + g_chunksums[warp >> 10];  // global segment end
    int i = end - cnt;

    float4 acc = make_float4(0.f, 0.f, 0.f, 0.f);

    // unrolled by 2 for MLP
    for (; i + 1 < end; i += 2) {
        const int2 e0 = g_sorted[i];
        const int2 e1 = g_sorted[i + 1];
        const uint2 r0 = *((const uint2*)(g_th + (size_t)e0.x * (F_OUT / 2)) + lane);
        const uint2 r1 = *((const uint2*)(g_th + (size_t)e1.x * (F_OUT / 2)) + lane);
        const float v0 = __int_as_float(e0.y);
        const float v1 = __int_as_float(e1.y);

        float2 f00 = __half22float2(*(const __half2*)&r0.x);
        float2 f01 = __half22float2(*(const __half2*)&r0.y);
        acc.x = fmaf(v0, f00.x, acc.x);
        acc.y = fmaf(v0, f00.y, acc.y);
        acc.z = fmaf(v0, f01.x, acc.z);
        acc.w = fmaf(v0, f01.y, acc.w);

        float2 f10 = __half22float2(*(const __half2*)&r1.x);
        float2 f11 = __half22float2(*(const __half2*)&r1.y);
        acc.x = fmaf(v1, f10.x, acc.x);
        acc.y = fmaf(v1, f10.y, acc.y);
        acc.z = fmaf(v1, f11.x, acc.z);
        acc.w = fmaf(v1, f11.y, acc.w);
    }
    if (i < end) {
        const int2 e0 = g_sorted[i];
        const uint2 r0 = *((const uint2*)(g_th + (size_t)e0.x * (F_OUT / 2)) + lane);
        const float v0 = __int_as_float(e0.y);
        float2 f00 = __half22float2(*(const __half2*)&r0.x);
        float2 f01 = __half22float2(*(const __half2*)&r0.y);
        acc.x = fmaf(v0, f00.x, acc.x);
        acc.y = fmaf(v0, f00.y, acc.y);
        acc.z = fmaf(v0, f01.x, acc.z);
        acc.w = fmaf(v0, f01.y, acc.w);
    }

    *((float4*)(out + (size_t)warp * F_OUT) + lane) = acc;  // rows w/o edges -> zeros
}

// ============================================================================
// Launch
// ============================================================================
extern "C" void kernel_launch(void* const* d_in, const int* in_sizes, int n_in,
                              void* d_out, int out_size)
{
    const float* X    = (const float*)d_in[0];
    const int*   er   = (const int*)  d_in[1];
    const int*   ec   = (const int*)  d_in[2];
    const float* ev   = (const float*)d_in[3];
    const float* W    = (const float*)d_in[4];
    const float* bias = (const float*)d_in[5];
    float* out = (float*)d_out;

    const int M = in_sizes[0] / F_IN;   // 100000
    const int E = in_sizes[1];          // 1600000
    const int nchunks = (M + 1023) / 1024;

    // CSR build
    zero_counts_kernel<<<(M + 255) / 256, 256>>>(M);
    hist_kernel<<<(E + 255) / 256, 256>>>(er, E);
    scan1_kernel<<<nchunks, 1024>>>(M);
    scan2_kernel<<<1, 256>>>(nchunks);
    fill_kernel<<<(E + 255) / 256, 256>>>(er, ec, ev, E);

    // GEMM (independent of CSR build)
    gemm_tf32_kernel<<<(M + BM - 1) / BM, 256>>>(X, W, bias, M);

    // row-major reduction, each output row written exactly once
    const int gwarps_per_block = 256 / 32;
    gather_kernel<<<(M + gwarps_per_block - 1) / gwarps_per_block, 256>>>(out, M);
}

// round 5
// speedup vs baseline: 2.5728x; 1.2989x over previous
#include <cuda_runtime.h>
#include <cuda_bf16.h>
#include <cuda_fp16.h>
#include <cstdint>

// N = 100000, E = 1,600,000, F_IN = 256, F_OUT = 128
// d_in: X [N*256] f32, edge_rows [E] i32, edge_cols [E] i32, edge_vals [E] f32,
//       W [128*256] f32, b [128] f32.  d_out: [N*128] f32.

#define F_IN   256
#define F_OUT  128
#define MAX_N  100000
#define MAX_E  1600000

// -------------------- device scratch (no allocs allowed) --------------------
__device__ __half2 g_th[(size_t)MAX_N * (F_OUT / 2)];   // transformed, fp16 (25.6 MB)
__device__ int   g_counts[MAX_N];                        // per-row degree
__device__ int   g_offsets[MAX_N];                       // chunk-local excl scan; after fill = chunk-local END
__device__ int   g_chunksums[256];                       // chunk bases (after scan2)
__device__ int2  g_sorted[MAX_E];                        // (col, val_bits) grouped by row

// ============================================================================
// Phase 1: TF32 tensor-core GEMM, 2-stage cp.async pipeline.
// Block tile 128x128, BK=32, 256 threads (8 warps), warp tile 64x32,
// mma.sync.m16n8k8. X fed via cp.async (truncated tf32), W via LDG+cvt.rna+STS.
// ============================================================================
#define BM 128
#define BN 128
#define BK 32
#define BKP 36   // padded smem row stride (floats), 16B-aligned

__device__ __forceinline__ float to_tf32(float f) {
    unsigned u;
    asm("cvt.rna.tf32.f32 %0, %1;" : "=r"(u) : "f"(f));
    return __uint_as_float(u);
}

__device__ __forceinline__ void cp_async16(float* smem_dst, const float* gsrc, bool valid) {
    unsigned s = (unsigned)__cvta_generic_to_shared(smem_dst);
    int sz = valid ? 16 : 0;
    asm volatile("cp.async.cg.shared.global [%0], [%1], 16, %2;\n"
                 :: "r"(s), "l"(gsrc), "r"(sz));
}

__device__ __forceinline__ void mma_tf32(
    float& c0, float& c1, float& c2, float& c3,
    unsigned a0, unsigned a1, unsigned a2, unsigned a3,
    unsigned b0, unsigned b1)
{
    asm volatile(
        "mma.sync.aligned.m16n8k8.row.col.f32.tf32.tf32.f32 "
        "{%0,%1,%2,%3}, {%4,%5,%6,%7}, {%8,%9}, {%0,%1,%2,%3};"
        : "+f"(c0), "+f"(c1), "+f"(c2), "+f"(c3)
        : "r"(a0), "r"(a1), "r"(a2), "r"(a3), "r"(b0), "r"(b1));
}

__global__ __launch_bounds__(256, 2) void gemm_tf32_kernel(
    const float* __restrict__ X,
    const float* __restrict__ W,
    const float* __restrict__ bias,
    int M)
{
    __shared__ __align__(16) float Xs[2][BM][BKP];
    __shared__ __align__(16) float Ws[2][BN][BKP];

    const int tid    = threadIdx.x;
    const int wid    = tid >> 5;
    const int lane   = tid & 31;
    const int warp_m = wid & 1;    // 2 warps in m: 64 rows each
    const int warp_n = wid >> 1;   // 4 warps in n: 32 cols each
    const int g4     = lane >> 2;
    const int tig    = lane & 3;
    const int m0     = blockIdx.x * BM;

    // loader mapping: thread -> (row, 16-wide k half)
    const int lrow = tid >> 1;           // 0..127
    const int lkb  = (tid & 1) << 4;     // 0 or 16
    const int mrow = m0 + lrow;
    const bool mvalid = (mrow < M);
    const float* xrow = X + (size_t)(mvalid ? mrow : 0) * F_IN + lkb;
    const float* wrow = W + (size_t)lrow * F_IN + lkb;

    float c[4][4][4];
#pragma unroll
    for (int mt = 0; mt < 4; ++mt)
#pragma unroll
        for (int nt = 0; nt < 4; ++nt)
#pragma unroll
            for (int i = 0; i < 4; ++i) c[mt][nt][i] = 0.0f;

    float wreg[16];

    // ---- prologue: stage 0 ----
#pragma unroll
    for (int i = 0; i < 4; ++i)
        cp_async16(&Xs[0][lrow][lkb + i * 4], xrow + i * 4, mvalid);
    asm volatile("cp.async.commit_group;\n" ::: "memory");
    {
        *(float4*)&wreg[0]  = *(const float4*)(wrow + 0);
        *(float4*)&wreg[4]  = *(const float4*)(wrow + 4);
        *(float4*)&wreg[8]  = *(const float4*)(wrow + 8);
        *(float4*)&wreg[12] = *(const float4*)(wrow + 12);
#pragma unroll
        for (int i = 0; i < 16; ++i) Ws[0][lrow][lkb + i] = to_tf32(wreg[i]);
    }
    asm volatile("cp.async.wait_group 0;\n" ::: "memory");
    __syncthreads();

    const int NITER = F_IN / BK;   // 8
#pragma unroll
    for (int it = 0; it < NITER; ++it) {
        const int buf = it & 1;
        const int nxt = buf ^ 1;

        // ---- issue next-stage loads ----
        if (it + 1 < NITER) {
            const int k1 = (it + 1) * BK;
#pragma unroll
            for (int i = 0; i < 4; ++i)
                cp_async16(&Xs[nxt][lrow][lkb + i * 4], xrow + k1 + i * 4, mvalid);
            asm volatile("cp.async.commit_group;\n" ::: "memory");
            *(float4*)&wreg[0]  = *(const float4*)(wrow + k1 + 0);
            *(float4*)&wreg[4]  = *(const float4*)(wrow + k1 + 4);
            *(float4*)&wreg[8]  = *(const float4*)(wrow + k1 + 8);
            *(float4*)&wreg[12] = *(const float4*)(wrow + k1 + 12);
        }

        // ---- compute on current stage: 4 k-groups of 8 ----
#pragma unroll
        for (int g = 0; g < 4; ++g) {
            const int kc = (g << 3) + tig;
            unsigned b0[4], b1[4];
#pragma unroll
            for (int nt = 0; nt < 4; ++nt) {
                const int n = warp_n * 32 + nt * 8 + g4;
                b0[nt] = __float_as_uint(Ws[buf][n][kc]);
                b1[nt] = __float_as_uint(Ws[buf][n][kc + 4]);
            }
#pragma unroll
            for (int mt = 0; mt < 4; ++mt) {
                const int r = warp_m * 64 + mt * 16 + g4;
                const unsigned a0 = __float_as_uint(Xs[buf][r][kc]);
                const unsigned a1 = __float_as_uint(Xs[buf][r + 8][kc]);
                const unsigned a2 = __float_as_uint(Xs[buf][r][kc + 4]);
                const unsigned a3 = __float_as_uint(Xs[buf][r + 8][kc + 4]);
#pragma unroll
                for (int nt = 0; nt < 4; ++nt)
                    mma_tf32(c[mt][nt][0], c[mt][nt][1], c[mt][nt][2], c[mt][nt][3],
                             a0, a1, a2, a3, b0[nt], b1[nt]);
            }
        }

        // ---- store next-stage W, then barrier ----
        if (it + 1 < NITER) {
#pragma unroll
            for (int i = 0; i < 16; ++i) Ws[nxt][lrow][lkb + i] = to_tf32(wreg[i]);
            asm volatile("cp.async.wait_group 0;\n" ::: "memory");
            __syncthreads();
        }
    }

    // ---- epilogue: bias + fp16 store ----
#pragma unroll
    for (int nt = 0; nt < 4; ++nt) {
        const int col = warp_n * 32 + nt * 8 + tig * 2;
        const float bx = bias[col], by = bias[col + 1];
#pragma unroll
        for (int mt = 0; mt < 4; ++mt) {
            const int row = m0 + warp_m * 64 + mt * 16 + g4;
            if (row < M) {
                g_th[(size_t)row * (F_OUT / 2) + (col >> 1)] =
                    __floats2half2_rn(c[mt][nt][0] + bx, c[mt][nt][1] + by);
            }
            if (row + 8 < M) {
                g_th[(size_t)(row + 8) * (F_OUT / 2) + (col >> 1)] =
                    __floats2half2_rn(c[mt][nt][2] + bx, c[mt][nt][3] + by);
            }
        }
    }
}

// ============================================================================
// Phase 2: CSR build + warp-per-row gather (no float atomics)
// ============================================================================
__global__ void hist_kernel(const int* __restrict__ rows, int E) {
    int i = blockIdx.x * blockDim.x + threadIdx.x;
    if (i < E) atomicAdd(&g_counts[rows[i]], 1);
}

// per-1024 chunk exclusive scan of counts -> offsets (shuffle-based)
__global__ __launch_bounds__(1024) void scan1_kernel(int n) {
    __shared__ int wsum[32];
    const int t   = threadIdx.x;
    const int gid = blockIdx.x * 1024 + t;
    const int v   = (gid < n) ? g_counts[gid] : 0;

    int x = v;
#pragma unroll
    for (int d = 1; d < 32; d <<= 1) {
        int y = __shfl_up_sync(0xffffffffu, x, d);
        if ((t & 31) >= d) x += y;
    }
    if ((t & 31) == 31) wsum[t >> 5] = x;
    __syncthreads();
    if (t < 32) {
        int s = wsum[t];
#pragma unroll
        for (int d = 1; d < 32; d <<= 1) {
            int y = __shfl_up_sync(0xffffffffu, s, d);
            if (t >= d) s += y;
        }
        wsum[t] = s;   // inclusive warp sums
    }
    __syncthreads();
    const int base = (t >= 32) ? wsum[(t >> 5) - 1] : 0;
    const int incl = x + base;
    if (gid < n) g_offsets[gid] = incl - v;         // chunk-local exclusive
    if (t == 1023) g_chunksums[blockIdx.x] = incl;  // chunk total
}

// exclusive scan of up to 128 chunk totals (shuffle-based, 128 threads)
__global__ __launch_bounds__(128) void scan2_kernel(int nchunks) {
    __shared__ int wsum[4];
    const int t = threadIdx.x;
    const int v = (t < nchunks) ? g_chunksums[t] : 0;

    int x = v;
#pragma unroll
    for (int d = 1; d < 32; d <<= 1) {
        int y = __shfl_up_sync(0xffffffffu, x, d);
        if ((t & 31) >= d) x += y;
    }
    if ((t & 31) == 31) wsum[t >> 5] = x;
    __syncthreads();
    int base = 0;
    if ((t >> 5) > 0) base = wsum[0];
    if ((t >> 5) > 1) base += wsum[1];
    if ((t >> 5) > 2) base += wsum[2];
    if (t < nchunks) g_chunksums[t] = x + base - v;   // exclusive
}

// scatter edges into row-grouped order (chunk base folded in here)
__global__ void fill_kernel(const int* __restrict__ rows,
                            const int* __restrict__ cols,
                            const float* __restrict__ vals, int E) {
    int e = blockIdx.x * blockDim.x + threadIdx.x;
    if (e < E) {
        const int r = rows[e];
        const int pos = atomicAdd(&g_offsets[r], 1) + g_chunksums[r >> 10];
        g_sorted[pos] = make_int2(cols[e], __float_as_int(vals[e]));
    }
}

// one warp per output row: out[r] = sum val * transformed_fp16[col]
__global__ __launch_bounds__(256) void gather_kernel(float* __restrict__ out, int N) {
    const int warp = (int)((blockIdx.x * (unsigned)blockDim.x + threadIdx.x) >> 5);
    const int lane = threadIdx.x & 31;
    if (warp >= N) return;

    const int cnt = g_counts[warp];
    const int end = g_offsets[warp] + g_chunksums[warp >> 10];  // global segment end
    int i = end - cnt;

    float4 acc = make_float4(0.f, 0.f, 0.f, 0.f);

    for (; i + 1 < end; i += 2) {
        const int2 e0 = g_sorted[i];
        const int2 e1 = g_sorted[i + 1];
        const uint2 r0 = *((const uint2*)(g_th + (size_t)e0.x * (F_OUT / 2)) + lane);
        const uint2 r1 = *((const uint2*)(g_th + (size_t)e1.x * (F_OUT / 2)) + lane);
        const float v0 = __int_as_float(e0.y);
        const float v1 = __int_as_float(e1.y);

        float2 f00 = __half22float2(*(const __half2*)&r0.x);
        float2 f01 = __half22float2(*(const __half2*)&r0.y);
        acc.x = fmaf(v0, f00.x, acc.x);
        acc.y = fmaf(v0, f00.y, acc.y);
        acc.z = fmaf(v0, f01.x, acc.z);
        acc.w = fmaf(v0, f01.y, acc.w);

        float2 f10 = __half22float2(*(const __half2*)&r1.x);
        float2 f11 = __half22float2(*(const __half2*)&r1.y);
        acc.x = fmaf(v1, f10.x, acc.x);
        acc.y = fmaf(v1, f10.y, acc.y);
        acc.z = fmaf(v1, f11.x, acc.z);
        acc.w = fmaf(v1, f11.y, acc.w);
    }
    if (i < end) {
        const int2 e0 = g_sorted[i];
        const uint2 r0 = *((const uint2*)(g_th + (size_t)e0.x * (F_OUT / 2)) + lane);
        const float v0 = __int_as_float(e0.y);
        float2 f00 = __half22float2(*(const __half2*)&r0.x);
        float2 f01 = __half22float2(*(const __half2*)&r0.y);
        acc.x = fmaf(v0, f00.x, acc.x);
        acc.y = fmaf(v0, f00.y, acc.y);
        acc.z = fmaf(v0, f01.x, acc.z);
        acc.w = fmaf(v0, f01.y, acc.w);
    }

    *((float4*)(out + (size_t)warp * F_OUT) + lane) = acc;  // rows w/o edges -> zeros
}

// ============================================================================
// Launch
// ============================================================================
extern "C" void kernel_launch(void* const* d_in, const int* in_sizes, int n_in,
                              void* d_out, int out_size)
{
    const float* X    = (const float*)d_in[0];
    const int*   er   = (const int*)  d_in[1];
    const int*   ec   = (const int*)  d_in[2];
    const float* ev   = (const float*)d_in[3];
    const float* W    = (const float*)d_in[4];
    const float* bias = (const float*)d_in[5];
    float* out = (float*)d_out;

    const int M = in_sizes[0] / F_IN;   // 100000
    const int E = in_sizes[1];          // 1600000
    const int nchunks = (M + 1023) / 1024;

    // GEMM first (independent of CSR build)
    gemm_tf32_kernel<<<(M + BM - 1) / BM, 256>>>(X, W, bias, M);

    // CSR build
    void* caddr = nullptr;
    cudaGetSymbolAddress(&caddr, g_counts);
    cudaMemsetAsync(caddr, 0, (size_t)M * sizeof(int));
    hist_kernel<<<(E + 255) / 256, 256>>>(er, E);
    scan1_kernel<<<nchunks, 1024>>>(M);
    scan2_kernel<<<1, 128>>>(nchunks);
    fill_kernel<<<(E + 255) / 256, 256>>>(er, ec, ev, E);

    // row-major reduction, each output row written exactly once
    const int gwarps_per_block = 256 / 32;
    gather_kernel<<<(M + gwarps_per_block - 1) / gwarps_per_block, 256>>>(out, M);
}